// round 16
// baseline (speedup 1.0000x reference)
#include <cuda_runtime.h>
#include <cuda_bf16.h>
#include <cuda_fp16.h>
#include <cstdint>

// Problem constants (match reference_code)
#define NN 50000
#define EE 800000
#define FIN 256
#define FOUT 64

#define NBLK 49   // ceil(NN / 1024)

// Scratch (no cudaMalloc allowed) — static __device__ globals.
__device__ int    g_cnt[NN];          // in-degree (w/o self loop)
__device__ int    g_fill[NN];         // bucket fill cursor (pre-init to offsets)
__device__ int    g_off[NN + 1];      // CSR offsets
__device__ int    g_bsum[64];         // per-block sums for scan
__device__ int    g_nbr[EE];          // CSR: src node per incoming edge (4B/edge)
__device__ float  g_deg[NN];          // dinv = rsqrt(deg)
__device__ __half g_h16[NN * FOUT];   // h = x @ W, fp16 (128B per row)

// ---------------------------------------------------------------------------
__device__ __forceinline__ uint32_t pk2(float lo, float hi) {
    uint32_t d;
    asm("cvt.rn.bf16x2.f32 %0, %1, %2;" : "=r"(d) : "f"(hi), "f"(lo));
    return d;
}
__device__ __forceinline__ float f_lo16(uint32_t u) { return __uint_as_float(u << 16); }
__device__ __forceinline__ float f_hi16(uint32_t u) { return __uint_as_float(u & 0xffff0000u); }

__device__ __forceinline__ void mma_bf16(float* c, const uint32_t* a, uint32_t b0, uint32_t b1) {
    asm volatile(
        "mma.sync.aligned.m16n8k16.row.col.f32.bf16.bf16.f32 "
        "{%0,%1,%2,%3}, {%4,%5,%6,%7}, {%8,%9}, {%0,%1,%2,%3};"
        : "+f"(c[0]), "+f"(c[1]), "+f"(c[2]), "+f"(c[3])
        : "r"(a[0]), "r"(a[1]), "r"(a[2]), "r"(a[3]), "r"(b0), "r"(b1));
}

// ---------------------------------------------------------------------------
// K1: zero counters
__global__ void k_zero() {
    int i = blockIdx.x * blockDim.x + threadIdx.x;
    if (i < NN) g_cnt[i] = 0;
}

// K2: in-degree count over edge dst (4 edges/thread, int4 loads)
__global__ void k_count(const int* __restrict__ dst) {
    int e0 = (blockIdx.x * blockDim.x + threadIdx.x) * 4;
    if (e0 >= EE) return;
    int4 d4 = *reinterpret_cast<const int4*>(dst + e0);
    atomicAdd(&g_cnt[d4.x], 1);
    atomicAdd(&g_cnt[d4.y], 1);
    atomicAdd(&g_cnt[d4.z], 1);
    atomicAdd(&g_cnt[d4.w], 1);
}

// K3a: per-block (1024 elems) sums, coalesced
__global__ __launch_bounds__(1024) void k_scan_a() {
    __shared__ int ws[32];
    const int t = threadIdx.x;
    int idx = blockIdx.x * 1024 + t;
    int v = (idx < NN) ? g_cnt[idx] : 0;
    for (int o = 16; o > 0; o >>= 1) v += __shfl_down_sync(0xffffffffu, v, o);
    if ((t & 31) == 0) ws[t >> 5] = v;
    __syncthreads();
    if (t < 32) {
        int s = ws[t];
        for (int o = 16; o > 0; o >>= 1) s += __shfl_down_sync(0xffffffffu, s, o);
        if (t == 0) g_bsum[blockIdx.x] = s;
    }
}

// K3b: per-block exclusive scan -> g_off, g_fill (cursor), g_deg.
__global__ __launch_bounds__(1024) void k_scan_c() {
    __shared__ int ws[32];
    __shared__ int bpre_s;
    const int t = threadIdx.x;
    const int lane = t & 31;
    const int wid = t >> 5;
    int idx = blockIdx.x * 1024 + t;
    int c = (idx < NN) ? g_cnt[idx] : 0;

    int incl = c;
    for (int o = 1; o < 32; o <<= 1) {
        int u = __shfl_up_sync(0xffffffffu, incl, o);
        if (lane >= o) incl += u;
    }
    if (lane == 31) ws[wid] = incl;

    if (wid == 1) {
        int accp = 0;
        for (int j = lane; j < blockIdx.x; j += 32) accp += g_bsum[j];
        for (int o = 16; o > 0; o >>= 1) accp += __shfl_down_sync(0xffffffffu, accp, o);
        if (lane == 0) bpre_s = accp;
    }
    __syncthreads();
    if (wid == 0) {
        int wv = ws[lane];
        for (int o = 1; o < 32; o <<= 1) {
            int u = __shfl_up_sync(0xffffffffu, wv, o);
            if (lane >= o) wv += u;
        }
        ws[lane] = wv;
    }
    __syncthreads();
    int excl = incl - c + (wid ? ws[wid - 1] : 0);

    if (idx < NN) {
        int off = bpre_s + excl;
        g_off[idx]  = off;
        g_fill[idx] = off;
        g_deg[idx]  = rsqrtf((float)(c + 1));
    }
    if (blockIdx.x == 0 && t == 0) g_off[NN] = EE;
}

// K4: bucket fill — cursor holds offsets; 4 edges/thread; 4B/edge store.
__global__ void k_fill(const int* __restrict__ src, const int* __restrict__ dst) {
    int e0 = (blockIdx.x * blockDim.x + threadIdx.x) * 4;
    if (e0 >= EE) return;
    int4 s4 = *reinterpret_cast<const int4*>(src + e0);
    int4 d4 = *reinterpret_cast<const int4*>(dst + e0);
    int p0 = atomicAdd(&g_fill[d4.x], 1);
    int p1 = atomicAdd(&g_fill[d4.y], 1);
    int p2 = atomicAdd(&g_fill[d4.z], 1);
    int p3 = atomicAdd(&g_fill[d4.w], 1);
    g_nbr[p0] = s4.x;
    g_nbr[p1] = s4.y;
    g_nbr[p2] = s4.z;
    g_nbr[p3] = s4.w;
}

// ---------------------------------------------------------------------------
// K5: mma.sync bf16 GEMM, split-bf16, permuted-K fragments.
// R15 shell + two deltas:
//  (a) branch-free double-buffered A loads (next offset is a compile-time
//      constant per unrolled iter; s=15 load folds away entirely),
//  (b) B-frags interleaved as uint4 {h01,h23,l01,l23} at stride 68 uint4/n:
//      one LDS.128 per nt (bank-conflict-free) instead of two LDS.64.

#define BF_STRIDE 68                        // uint4 units per n
#define GEMM_SMEM (64 * BF_STRIDE * 16)     // bytes = 69632 (same as before)

__global__ __launch_bounds__(512, 2) void k_gemm_mma(
    const float* __restrict__ x, const float* __restrict__ W)
{
    extern __shared__ __align__(16) uint4 Bf[];   // [64][BF_STRIDE]

    const int t    = threadIdx.x;
    const int wid  = t >> 5;
    const int lane = t & 31;
    const int g    = lane >> 2;
    const int tig  = lane & 3;

    // ---- stage W as interleaved uint4 b-fragments: 4096 / 512 thr = 8 each ----
#pragma unroll
    for (int i = 0; i < 8; ++i) {
        int e  = t + i * 512;
        int n  = e >> 6;              // 0..63
        int rem = e & 63;
        int s  = rem >> 2;            // k-step 0..15
        int tg = rem & 3;             // tig slot
        int kb = s * 16 + tg * 4;     // permuted-k fragment base
        float w0 = W[kb * FOUT + n];
        float w1 = W[(kb + 1) * FOUT + n];
        float w2 = W[(kb + 2) * FOUT + n];
        float w3 = W[(kb + 3) * FOUT + n];
        uint32_t h01 = pk2(w0, w1);
        uint32_t h23 = pk2(w2, w3);
        uint32_t l01 = pk2(w0 - f_lo16(h01), w1 - f_hi16(h01));
        uint32_t l23 = pk2(w2 - f_lo16(h23), w3 - f_hi16(h23));
        Bf[n * BF_STRIDE + s * 4 + tg] = make_uint4(h01, h23, l01, l23);
    }
    __syncthreads();

    const int stripe = wid & 7;
    const int nhalf  = wid >> 3;
    const int row0   = blockIdx.x * 128 + stripe * 16;

    const int row1 = row0 + g;
    const int row2 = row1 + 8;
    const bool v1 = (row1 < NN);
    const bool v2 = (row2 < NN);
    const float* xr1 = x + (size_t)row1 * FIN;
    const float* xr2 = x + (size_t)row2 * FIN;

    float acc[4][4];
#pragma unroll
    for (int i = 0; i < 4; ++i)
#pragma unroll
        for (int j = 0; j < 4; ++j) acc[i][j] = 0.0f;

    // prologue: step-0 A loads
    float4 q1 = v1 ? *reinterpret_cast<const float4*>(xr1 + tig * 4)
                   : make_float4(0.f, 0.f, 0.f, 0.f);
    float4 q2 = v2 ? *reinterpret_cast<const float4*>(xr2 + tig * 4)
                   : make_float4(0.f, 0.f, 0.f, 0.f);

#pragma unroll
    for (int s = 0; s < 16; ++s) {
        // convert current step (q1,q2 die here)
        uint32_t a_hi[4], a_lo[4];
        a_hi[0] = pk2(q1.x, q1.y); a_lo[0] = pk2(q1.x - f_lo16(a_hi[0]), q1.y - f_hi16(a_hi[0]));
        a_hi[1] = pk2(q2.x, q2.y); a_lo[1] = pk2(q2.x - f_lo16(a_hi[1]), q2.y - f_hi16(a_hi[1]));
        a_hi[2] = pk2(q1.z, q1.w); a_lo[2] = pk2(q1.z - f_lo16(a_hi[2]), q1.w - f_hi16(a_hi[2]));
        a_hi[3] = pk2(q2.z, q2.w); a_lo[3] = pk2(q2.z - f_lo16(a_hi[3]), q2.w - f_hi16(a_hi[3]));

        // branch-free next-step loads: kn is a compile-time constant per iter;
        // for s==15 the (s<15 && vX) predicate folds to false -> no load at all.
        {
            const int kn = ((s + 1) & 15) * 16 + tig * 4;
            float4 p1 = (s < 15 && v1) ? *reinterpret_cast<const float4*>(xr1 + kn)
                                       : make_float4(0.f, 0.f, 0.f, 0.f);
            float4 p2 = (s < 15 && v2) ? *reinterpret_cast<const float4*>(xr2 + kn)
                                       : make_float4(0.f, 0.f, 0.f, 0.f);

            const int fbase = s * 4 + tig;
#pragma unroll
            for (int nt = 0; nt < 4; ++nt) {
                uint4 f = Bf[(nhalf * 32 + nt * 8 + g) * BF_STRIDE + fbase];
                mma_bf16(acc[nt], a_hi, f.x, f.y);   // hi*hi
                mma_bf16(acc[nt], a_hi, f.z, f.w);   // hi*lo
                mma_bf16(acc[nt], a_lo, f.x, f.y);   // lo*hi
            }
            q1 = p1;
            q2 = p2;
        }
    }

    // ---- epilogue: write h as fp16 ----
#pragma unroll
    for (int nt = 0; nt < 4; ++nt) {
        int c0 = nhalf * 32 + nt * 8 + tig * 2;
        if (v1) {
            __half2 hv = __floats2half2_rn(acc[nt][0], acc[nt][1]);
            *reinterpret_cast<__half2*>(&g_h16[(size_t)row1 * FOUT + c0]) = hv;
        }
        if (v2) {
            __half2 hv = __floats2half2_rn(acc[nt][2], acc[nt][3]);
            *reinterpret_cast<__half2*>(&g_h16[(size_t)row2 * FOUT + c0]) = hv;
        }
    }
}

// ---------------------------------------------------------------------------
// K6: CSR gather on fp16 h. 2 nodes/warp, fp32 accumulation, x4 unroll,
// predicated parallel tail. UNCHANGED from R15.
__global__ __launch_bounds__(256) void k_gather(
    const float* __restrict__ bias, float* __restrict__ out)
{
    const int warp = blockIdx.x * 8 + (threadIdx.x >> 5);
    const int lane = threadIdx.x & 31;
    const int half = lane >> 4;
    const int hl   = lane & 15;
    const int node = warp * 2 + half;
    if (node >= NN) return;

    const float dinv = g_deg[node];
    const int beg = g_off[node];
    const int end = g_off[node + 1];

    uint2 su = *reinterpret_cast<const uint2*>(&g_h16[(size_t)node * FOUT + hl * 4]);
    float2 s01 = __half22float2(*reinterpret_cast<__half2*>(&su.x));
    float2 s23 = __half22float2(*reinterpret_cast<__half2*>(&su.y));
    const float sl = dinv * dinv;
    float4 a = make_float4(s01.x * sl, s01.y * sl, s23.x * sl, s23.y * sl);

    int j = beg;
    for (; j + 4 <= end; j += 4) {
        int s0 = g_nbr[j];
        int s1 = g_nbr[j + 1];
        int s2 = g_nbr[j + 2];
        int s3 = g_nbr[j + 3];
        float n0 = dinv * g_deg[s0];
        float n1 = dinv * g_deg[s1];
        float n2 = dinv * g_deg[s2];
        float n3 = dinv * g_deg[s3];
        uint2 u0 = *reinterpret_cast<const uint2*>(&g_h16[(size_t)s0 * FOUT + hl * 4]);
        uint2 u1 = *reinterpret_cast<const uint2*>(&g_h16[(size_t)s1 * FOUT + hl * 4]);
        uint2 u2 = *reinterpret_cast<const uint2*>(&g_h16[(size_t)s2 * FOUT + hl * 4]);
        uint2 u3 = *reinterpret_cast<const uint2*>(&g_h16[(size_t)s3 * FOUT + hl * 4]);

        float2 f0a = __half22float2(*reinterpret_cast<__half2*>(&u0.x));
        float2 f0b = __half22float2(*reinterpret_cast<__half2*>(&u0.y));
        a.x = fmaf(f0a.x, n0, a.x); a.y = fmaf(f0a.y, n0, a.y);
        a.z = fmaf(f0b.x, n0, a.z); a.w = fmaf(f0b.y, n0, a.w);

        float2 f1a = __half22float2(*reinterpret_cast<__half2*>(&u1.x));
        float2 f1b = __half22float2(*reinterpret_cast<__half2*>(&u1.y));
        a.x = fmaf(f1a.x, n1, a.x); a.y = fmaf(f1a.y, n1, a.y);
        a.z = fmaf(f1b.x, n1, a.z); a.w = fmaf(f1b.y, n1, a.w);

        float2 f2a = __half22float2(*reinterpret_cast<__half2*>(&u2.x));
        float2 f2b = __half22float2(*reinterpret_cast<__half2*>(&u2.y));
        a.x = fmaf(f2a.x, n2, a.x); a.y = fmaf(f2a.y, n2, a.y);
        a.z = fmaf(f2b.x, n2, a.z); a.w = fmaf(f2b.y, n2, a.w);

        float2 f3a = __half22float2(*reinterpret_cast<__half2*>(&u3.x));
        float2 f3b = __half22float2(*reinterpret_cast<__half2*>(&u3.y));
        a.x = fmaf(f3a.x, n3, a.x); a.y = fmaf(f3a.y, n3, a.y);
        a.z = fmaf(f3b.x, n3, a.z); a.w = fmaf(f3b.y, n3, a.w);
    }
    if (j < end) {
        int i0 = j, i1 = j + 1, i2 = j + 2;
        int s0 = g_nbr[i0];
        int s1 = g_nbr[(i1 < end) ? i1 : i0];
        int s2 = g_nbr[(i2 < end) ? i2 : i0];
        float n0 = dinv * g_deg[s0];
        float n1 = (i1 < end) ? dinv * g_deg[s1] : 0.f;
        float n2 = (i2 < end) ? dinv * g_deg[s2] : 0.f;
        uint2 u0 = *reinterpret_cast<const uint2*>(&g_h16[(size_t)s0 * FOUT + hl * 4]);
        uint2 u1 = *reinterpret_cast<const uint2*>(&g_h16[(size_t)s1 * FOUT + hl * 4]);
        uint2 u2 = *reinterpret_cast<const uint2*>(&g_h16[(size_t)s2 * FOUT + hl * 4]);
        float2 f0a = __half22float2(*reinterpret_cast<__half2*>(&u0.x));
        float2 f0b = __half22float2(*reinterpret_cast<__half2*>(&u0.y));
        float2 f1a = __half22float2(*reinterpret_cast<__half2*>(&u1.x));
        float2 f1b = __half22float2(*reinterpret_cast<__half2*>(&u1.y));
        float2 f2a = __half22float2(*reinterpret_cast<__half2*>(&u2.x));
        float2 f2b = __half22float2(*reinterpret_cast<__half2*>(&u2.y));
        a.x = fmaf(f0a.x, n0, a.x); a.y = fmaf(f0a.y, n0, a.y);
        a.z = fmaf(f0b.x, n0, a.z); a.w = fmaf(f0b.y, n0, a.w);
        a.x = fmaf(f1a.x, n1, a.x); a.y = fmaf(f1a.y, n1, a.y);
        a.z = fmaf(f1b.x, n1, a.z); a.w = fmaf(f1b.y, n1, a.w);
        a.x = fmaf(f2a.x, n2, a.x); a.y = fmaf(f2a.y, n2, a.y);
        a.z = fmaf(f2b.x, n2, a.z); a.w = fmaf(f2b.y, n2, a.w);
    }

    float4 bb = *reinterpret_cast<const float4*>(bias + hl * 4);
    a.x = fmaxf(a.x + bb.x, 0.f);
    a.y = fmaxf(a.y + bb.y, 0.f);
    a.z = fmaxf(a.z + bb.z, 0.f);
    a.w = fmaxf(a.w + bb.w, 0.f);
    *reinterpret_cast<float4*>(&out[(size_t)node * FOUT + hl * 4]) = a;
}

// ---------------------------------------------------------------------------
// Launch topology: fork/join; gemm is the 4th API launch (profiled).
extern "C" void kernel_launch(void* const* d_in, const int* in_sizes, int n_in,
                              void* d_out, int out_size)
{
    const float* x   = (const float*)d_in[0];   // [N, 256]
    const int*   adj = (const int*)d_in[1];     // [2, E]
    const float* W   = (const float*)d_in[2];   // [256, 64]
    const float* b   = (const float*)d_in[3];   // [64]
    float*       out = (float*)d_out;           // [N, 64]

    const int* src = adj;
    const int* dst = adj + EE;

    static cudaStream_t s2 = nullptr;
    static cudaEvent_t evF = nullptr, evJ = nullptr;
    if (!s2) {
        cudaStreamCreateWithFlags(&s2, cudaStreamNonBlocking);
        cudaEventCreateWithFlags(&evF, cudaEventDisableTiming);
        cudaEventCreateWithFlags(&evJ, cudaEventDisableTiming);
        cudaFuncSetAttribute(k_gemm_mma,
                             cudaFuncAttributeMaxDynamicSharedMemorySize, GEMM_SMEM);
    }

    // fork
    cudaEventRecord(evF, 0);
    cudaStreamWaitEvent(s2, evF, 0);

    // s2: first part of CSR build
    k_zero<<<(NN + 255) / 256, 256, 0, s2>>>();
    k_count<<<(EE / 4 + 255) / 256, 256, 0, s2>>>(dst);
    k_scan_a<<<NBLK, 1024, 0, s2>>>();

    // main: GEMM — 4th API launch (profiled)
    k_gemm_mma<<<(NN + 127) / 128, 512, GEMM_SMEM>>>(x, W);

    // s2: rest of CSR build
    k_scan_c<<<NBLK, 1024, 0, s2>>>();
    k_fill<<<(EE / 4 + 255) / 256, 256, 0, s2>>>(src, dst);
    cudaEventRecord(evJ, s2);

    // join: gather needs both branches
    cudaStreamWaitEvent(0, evJ, 0);
    k_gather<<<(NN / 2 + 7) / 8, 256>>>(b, out);
}

// round 17
// speedup vs baseline: 1.2011x; 1.2011x over previous
#include <cuda_runtime.h>
#include <cuda_bf16.h>
#include <cuda_fp16.h>
#include <cstdint>

// Problem constants (match reference_code)
#define NN 50000
#define EE 800000
#define FIN 256
#define FOUT 64

#define NBLK 49   // ceil(NN / 1024)

// Scratch (no cudaMalloc allowed) — static __device__ globals.
__device__ int    g_cnt[NN];          // in-degree (w/o self loop)
__device__ int    g_fill[NN];         // bucket fill cursor (pre-init to offsets)
__device__ int    g_off[NN + 1];      // CSR offsets
__device__ int    g_bsum[64];         // per-block sums for scan
__device__ int    g_nbr[EE];          // CSR: src node per incoming edge (4B/edge)
__device__ float  g_deg[NN];          // dinv = rsqrt(deg)
__device__ __half g_h16[NN * FOUT];   // h = x @ W, fp16 (128B per row)

// ---------------------------------------------------------------------------
__device__ __forceinline__ uint32_t tf32b(float f) {
    uint32_t r;
    asm("cvt.rna.tf32.f32 %0, %1;" : "=r"(r) : "f"(f));
    return r;
}

__device__ __forceinline__ void mma_tf32(float* c,
                                         uint32_t a0, uint32_t a1, uint32_t a2, uint32_t a3,
                                         uint32_t b0, uint32_t b1) {
    asm volatile(
        "mma.sync.aligned.m16n8k8.row.col.f32.tf32.tf32.f32 "
        "{%0,%1,%2,%3}, {%4,%5,%6,%7}, {%8,%9}, {%0,%1,%2,%3};"
        : "+f"(c[0]), "+f"(c[1]), "+f"(c[2]), "+f"(c[3])
        : "r"(a0), "r"(a1), "r"(a2), "r"(a3), "r"(b0), "r"(b1));
}

// ---------------------------------------------------------------------------
// K1: zero counters
__global__ void k_zero() {
    int i = blockIdx.x * blockDim.x + threadIdx.x;
    if (i < NN) g_cnt[i] = 0;
}

// K2: in-degree count over edge dst (4 edges/thread, int4 loads)
__global__ void k_count(const int* __restrict__ dst) {
    int e0 = (blockIdx.x * blockDim.x + threadIdx.x) * 4;
    if (e0 >= EE) return;
    int4 d4 = *reinterpret_cast<const int4*>(dst + e0);
    atomicAdd(&g_cnt[d4.x], 1);
    atomicAdd(&g_cnt[d4.y], 1);
    atomicAdd(&g_cnt[d4.z], 1);
    atomicAdd(&g_cnt[d4.w], 1);
}

// K3a: per-block (1024 elems) sums, coalesced
__global__ __launch_bounds__(1024) void k_scan_a() {
    __shared__ int ws[32];
    const int t = threadIdx.x;
    int idx = blockIdx.x * 1024 + t;
    int v = (idx < NN) ? g_cnt[idx] : 0;
    for (int o = 16; o > 0; o >>= 1) v += __shfl_down_sync(0xffffffffu, v, o);
    if ((t & 31) == 0) ws[t >> 5] = v;
    __syncthreads();
    if (t < 32) {
        int s = ws[t];
        for (int o = 16; o > 0; o >>= 1) s += __shfl_down_sync(0xffffffffu, s, o);
        if (t == 0) g_bsum[blockIdx.x] = s;
    }
}

// K3b: per-block exclusive scan -> g_off, g_fill (cursor), g_deg.
__global__ __launch_bounds__(1024) void k_scan_c() {
    __shared__ int ws[32];
    __shared__ int bpre_s;
    const int t = threadIdx.x;
    const int lane = t & 31;
    const int wid = t >> 5;
    int idx = blockIdx.x * 1024 + t;
    int c = (idx < NN) ? g_cnt[idx] : 0;

    int incl = c;
    for (int o = 1; o < 32; o <<= 1) {
        int u = __shfl_up_sync(0xffffffffu, incl, o);
        if (lane >= o) incl += u;
    }
    if (lane == 31) ws[wid] = incl;

    if (wid == 1) {
        int accp = 0;
        for (int j = lane; j < blockIdx.x; j += 32) accp += g_bsum[j];
        for (int o = 16; o > 0; o >>= 1) accp += __shfl_down_sync(0xffffffffu, accp, o);
        if (lane == 0) bpre_s = accp;
    }
    __syncthreads();
    if (wid == 0) {
        int wv = ws[lane];
        for (int o = 1; o < 32; o <<= 1) {
            int u = __shfl_up_sync(0xffffffffu, wv, o);
            if (lane >= o) wv += u;
        }
        ws[lane] = wv;
    }
    __syncthreads();
    int excl = incl - c + (wid ? ws[wid - 1] : 0);

    if (idx < NN) {
        int off = bpre_s + excl;
        g_off[idx]  = off;
        g_fill[idx] = off;
        g_deg[idx]  = rsqrtf((float)(c + 1));
    }
    if (blockIdx.x == 0 && t == 0) g_off[NN] = EE;
}

// K4: bucket fill — cursor holds offsets; 4 edges/thread; 4B/edge store.
__global__ void k_fill(const int* __restrict__ src, const int* __restrict__ dst) {
    int e0 = (blockIdx.x * blockDim.x + threadIdx.x) * 4;
    if (e0 >= EE) return;
    int4 s4 = *reinterpret_cast<const int4*>(src + e0);
    int4 d4 = *reinterpret_cast<const int4*>(dst + e0);
    int p0 = atomicAdd(&g_fill[d4.x], 1);
    int p1 = atomicAdd(&g_fill[d4.y], 1);
    int p2 = atomicAdd(&g_fill[d4.z], 1);
    int p3 = atomicAdd(&g_fill[d4.w], 1);
    g_nbr[p0] = s4.x;
    g_nbr[p1] = s4.y;
    g_nbr[p2] = s4.z;
    g_nbr[p3] = s4.w;
}

// ---------------------------------------------------------------------------
// K5: TF32 mma.sync GEMM  h = x @ W.
// Proven simple-loop shell (512 thr, 16 warps = 8 m-stripes x 2 n-halves,
// acc[4][4]); per k16 step: 2 LDG.128 (A), 8 CVT tf32, 16 LDS.32 (B),
// 8 MMA m16n8k8 — no split-bf16 conversion chain.
// B smem [k][n] fp32 pad 65: staging stores AND b-frag loads conflict-free
// (load bank = 4*tig + g covers 0..31 exactly across the warp).
// Permuted-K: thread tig's float4 at k = s*16+tig*4 supplies both k8 frags:
//   MMA0 A={q1.x,q2.x,q1.y,q2.y} B={W[kb4][n],W[kb4+1][n]}
//   MMA1 A={q1.z,q2.z,q1.w,q2.w} B={W[kb4+2][n],W[kb4+3][n]}

#define BPAD 65
#define GEMM_SMEM (256 * BPAD * 4)   // 66560 bytes

__global__ __launch_bounds__(512, 2) void k_gemm_mma(
    const float* __restrict__ x, const float* __restrict__ W)
{
    extern __shared__ __align__(16) float Bs[];   // [256][BPAD], tf32 bits

    const int t    = threadIdx.x;
    const int wid  = t >> 5;
    const int lane = t & 31;
    const int g    = lane >> 2;
    const int tig  = lane & 3;

    // ---- stage W as tf32 bits, [k][n] pad-65 (coalesced, conflict-free) ----
#pragma unroll 8
    for (int it = 0; it < 32; ++it) {
        int idx = t + it * 512;
        int k = idx >> 6;
        int n = idx & 63;
        uint32_t tw = tf32b(W[k * FOUT + n]);
        Bs[k * BPAD + n] = __uint_as_float(tw);
    }
    __syncthreads();

    const int stripe = wid & 7;
    const int nhalf  = wid >> 3;
    const int row0   = blockIdx.x * 128 + stripe * 16;

    const int row1 = row0 + g;
    const int row2 = row1 + 8;
    const bool v1 = (row1 < NN);
    const bool v2 = (row2 < NN);
    const float* xr1 = x + (size_t)row1 * FIN;
    const float* xr2 = x + (size_t)row2 * FIN;

    float acc[4][4];
#pragma unroll
    for (int i = 0; i < 4; ++i)
#pragma unroll
        for (int j = 0; j < 4; ++j) acc[i][j] = 0.0f;

#pragma unroll 4
    for (int s = 0; s < 16; ++s) {
        const int kb4 = s * 16 + tig * 4;

        float4 q1 = v1 ? *reinterpret_cast<const float4*>(xr1 + kb4)
                       : make_float4(0.f, 0.f, 0.f, 0.f);
        float4 q2 = v2 ? *reinterpret_cast<const float4*>(xr2 + kb4)
                       : make_float4(0.f, 0.f, 0.f, 0.f);

        uint32_t a00 = tf32b(q1.x), a01 = tf32b(q1.y), a02 = tf32b(q1.z), a03 = tf32b(q1.w);
        uint32_t a10 = tf32b(q2.x), a11 = tf32b(q2.y), a12 = tf32b(q2.z), a13 = tf32b(q2.w);

#pragma unroll
        for (int nt = 0; nt < 4; ++nt) {
            int n = nhalf * 32 + nt * 8 + g;
            uint32_t b0 = __float_as_uint(Bs[(kb4 + 0) * BPAD + n]);
            uint32_t b1 = __float_as_uint(Bs[(kb4 + 1) * BPAD + n]);
            uint32_t b2 = __float_as_uint(Bs[(kb4 + 2) * BPAD + n]);
            uint32_t b3 = __float_as_uint(Bs[(kb4 + 3) * BPAD + n]);
            mma_tf32(acc[nt], a00, a10, a01, a11, b0, b1);
            mma_tf32(acc[nt], a02, a12, a03, a13, b2, b3);
        }
    }

    // ---- epilogue: write h as fp16 (same accumulator layout as m16n8k16) ----
#pragma unroll
    for (int nt = 0; nt < 4; ++nt) {
        int c0 = nhalf * 32 + nt * 8 + tig * 2;
        if (v1) {
            __half2 hv = __floats2half2_rn(acc[nt][0], acc[nt][1]);
            *reinterpret_cast<__half2*>(&g_h16[(size_t)row1 * FOUT + c0]) = hv;
        }
        if (v2) {
            __half2 hv = __floats2half2_rn(acc[nt][2], acc[nt][3]);
            *reinterpret_cast<__half2*>(&g_h16[(size_t)row2 * FOUT + c0]) = hv;
        }
    }
}

// ---------------------------------------------------------------------------
// K6: CSR gather on fp16 h. 2 nodes/warp, fp32 accumulation, x4 unroll,
// predicated parallel tail. UNCHANGED.
__global__ __launch_bounds__(256) void k_gather(
    const float* __restrict__ bias, float* __restrict__ out)
{
    const int warp = blockIdx.x * 8 + (threadIdx.x >> 5);
    const int lane = threadIdx.x & 31;
    const int half = lane >> 4;
    const int hl   = lane & 15;
    const int node = warp * 2 + half;
    if (node >= NN) return;

    const float dinv = g_deg[node];
    const int beg = g_off[node];
    const int end = g_off[node + 1];

    uint2 su = *reinterpret_cast<const uint2*>(&g_h16[(size_t)node * FOUT + hl * 4]);
    float2 s01 = __half22float2(*reinterpret_cast<__half2*>(&su.x));
    float2 s23 = __half22float2(*reinterpret_cast<__half2*>(&su.y));
    const float sl = dinv * dinv;
    float4 a = make_float4(s01.x * sl, s01.y * sl, s23.x * sl, s23.y * sl);

    int j = beg;
    for (; j + 4 <= end; j += 4) {
        int s0 = g_nbr[j];
        int s1 = g_nbr[j + 1];
        int s2 = g_nbr[j + 2];
        int s3 = g_nbr[j + 3];
        float n0 = dinv * g_deg[s0];
        float n1 = dinv * g_deg[s1];
        float n2 = dinv * g_deg[s2];
        float n3 = dinv * g_deg[s3];
        uint2 u0 = *reinterpret_cast<const uint2*>(&g_h16[(size_t)s0 * FOUT + hl * 4]);
        uint2 u1 = *reinterpret_cast<const uint2*>(&g_h16[(size_t)s1 * FOUT + hl * 4]);
        uint2 u2 = *reinterpret_cast<const uint2*>(&g_h16[(size_t)s2 * FOUT + hl * 4]);
        uint2 u3 = *reinterpret_cast<const uint2*>(&g_h16[(size_t)s3 * FOUT + hl * 4]);

        float2 f0a = __half22float2(*reinterpret_cast<__half2*>(&u0.x));
        float2 f0b = __half22float2(*reinterpret_cast<__half2*>(&u0.y));
        a.x = fmaf(f0a.x, n0, a.x); a.y = fmaf(f0a.y, n0, a.y);
        a.z = fmaf(f0b.x, n0, a.z); a.w = fmaf(f0b.y, n0, a.w);

        float2 f1a = __half22float2(*reinterpret_cast<__half2*>(&u1.x));
        float2 f1b = __half22float2(*reinterpret_cast<__half2*>(&u1.y));
        a.x = fmaf(f1a.x, n1, a.x); a.y = fmaf(f1a.y, n1, a.y);
        a.z = fmaf(f1b.x, n1, a.z); a.w = fmaf(f1b.y, n1, a.w);

        float2 f2a = __half22float2(*reinterpret_cast<__half2*>(&u2.x));
        float2 f2b = __half22float2(*reinterpret_cast<__half2*>(&u2.y));
        a.x = fmaf(f2a.x, n2, a.x); a.y = fmaf(f2a.y, n2, a.y);
        a.z = fmaf(f2b.x, n2, a.z); a.w = fmaf(f2b.y, n2, a.w);

        float2 f3a = __half22float2(*reinterpret_cast<__half2*>(&u3.x));
        float2 f3b = __half22float2(*reinterpret_cast<__half2*>(&u3.y));
        a.x = fmaf(f3a.x, n3, a.x); a.y = fmaf(f3a.y, n3, a.y);
        a.z = fmaf(f3b.x, n3, a.z); a.w = fmaf(f3b.y, n3, a.w);
    }
    if (j < end) {
        int i0 = j, i1 = j + 1, i2 = j + 2;
        int s0 = g_nbr[i0];
        int s1 = g_nbr[(i1 < end) ? i1 : i0];
        int s2 = g_nbr[(i2 < end) ? i2 : i0];
        float n0 = dinv * g_deg[s0];
        float n1 = (i1 < end) ? dinv * g_deg[s1] : 0.f;
        float n2 = (i2 < end) ? dinv * g_deg[s2] : 0.f;
        uint2 u0 = *reinterpret_cast<const uint2*>(&g_h16[(size_t)s0 * FOUT + hl * 4]);
        uint2 u1 = *reinterpret_cast<const uint2*>(&g_h16[(size_t)s1 * FOUT + hl * 4]);
        uint2 u2 = *reinterpret_cast<const uint2*>(&g_h16[(size_t)s2 * FOUT + hl * 4]);
        float2 f0a = __half22float2(*reinterpret_cast<__half2*>(&u0.x));
        float2 f0b = __half22float2(*reinterpret_cast<__half2*>(&u0.y));
        float2 f1a = __half22float2(*reinterpret_cast<__half2*>(&u1.x));
        float2 f1b = __half22float2(*reinterpret_cast<__half2*>(&u1.y));
        float2 f2a = __half22float2(*reinterpret_cast<__half2*>(&u2.x));
        float2 f2b = __half22float2(*reinterpret_cast<__half2*>(&u2.y));
        a.x = fmaf(f0a.x, n0, a.x); a.y = fmaf(f0a.y, n0, a.y);
        a.z = fmaf(f0b.x, n0, a.z); a.w = fmaf(f0b.y, n0, a.w);
        a.x = fmaf(f1a.x, n1, a.x); a.y = fmaf(f1a.y, n1, a.y);
        a.z = fmaf(f1b.x, n1, a.z); a.w = fmaf(f1b.y, n1, a.w);
        a.x = fmaf(f2a.x, n2, a.x); a.y = fmaf(f2a.y, n2, a.y);
        a.z = fmaf(f2b.x, n2, a.z); a.w = fmaf(f2b.y, n2, a.w);
    }

    float4 bb = *reinterpret_cast<const float4*>(bias + hl * 4);
    a.x = fmaxf(a.x + bb.x, 0.f);
    a.y = fmaxf(a.y + bb.y, 0.f);
    a.z = fmaxf(a.z + bb.z, 0.f);
    a.w = fmaxf(a.w + bb.w, 0.f);
    *reinterpret_cast<float4*>(&out[(size_t)node * FOUT + hl * 4]) = a;
}

// ---------------------------------------------------------------------------
// Launch topology: fork/join; gemm is the 4th API launch (profiled).
extern "C" void kernel_launch(void* const* d_in, const int* in_sizes, int n_in,
                              void* d_out, int out_size)
{
    const float* x   = (const float*)d_in[0];   // [N, 256]
    const int*   adj = (const int*)d_in[1];     // [2, E]
    const float* W   = (const float*)d_in[2];   // [256, 64]
    const float* b   = (const float*)d_in[3];   // [64]
    float*       out = (float*)d_out;           // [N, 64]

    const int* src = adj;
    const int* dst = adj + EE;

    static cudaStream_t s2 = nullptr;
    static cudaEvent_t evF = nullptr, evJ = nullptr;
    if (!s2) {
        cudaStreamCreateWithFlags(&s2, cudaStreamNonBlocking);
        cudaEventCreateWithFlags(&evF, cudaEventDisableTiming);
        cudaEventCreateWithFlags(&evJ, cudaEventDisableTiming);
        cudaFuncSetAttribute(k_gemm_mma,
                             cudaFuncAttributeMaxDynamicSharedMemorySize, GEMM_SMEM);
    }

    // fork
    cudaEventRecord(evF, 0);
    cudaStreamWaitEvent(s2, evF, 0);

    // s2: first part of CSR build
    k_zero<<<(NN + 255) / 256, 256, 0, s2>>>();
    k_count<<<(EE / 4 + 255) / 256, 256, 0, s2>>>(dst);
    k_scan_a<<<NBLK, 1024, 0, s2>>>();

    // main: GEMM — 4th API launch (profiled)
    k_gemm_mma<<<(NN + 127) / 128, 512, GEMM_SMEM>>>(x, W);

    // s2: rest of CSR build
    k_scan_c<<<NBLK, 1024, 0, s2>>>();
    k_fill<<<(EE / 4 + 255) / 256, 256, 0, s2>>>(src, dst);
    cudaEventRecord(evJ, s2);

    // join: gather needs both branches
    cudaStreamWaitEvent(0, evJ, 0);
    k_gather<<<(NN / 2 + 7) / 8, 256>>>(b, out);
}